// round 8
// baseline (speedup 1.0000x reference)
#include <cuda_runtime.h>
#include <cuda_bf16.h>
#include <math.h>
#include <stdint.h>

#define BATCH 4
#define NTOK  2048
#define DMODEL 1024
#define HEADS 16
#define DH    64
#define INNER 1024
#define SCALE 0.125f   /* 64^-0.5 */

typedef unsigned long long u64;

// ======================= f32x2 helpers (attention) ==========================
__device__ __forceinline__ u64 pack2(float x) {
    u64 r; asm("mov.b64 %0, {%1, %1};" : "=l"(r) : "f"(x)); return r;
}
__device__ __forceinline__ u64 pack2f(float x, float y) {
    u64 r; asm("mov.b64 %0, {%1, %2};" : "=l"(r) : "f"(x), "f"(y)); return r;
}
__device__ __forceinline__ float2 unpack2(u64 a) {
    float2 f; asm("mov.b64 {%0, %1}, %2;" : "=f"(f.x), "=f"(f.y) : "l"(a)); return f;
}
__device__ __forceinline__ void ffma2(u64 &d, u64 a, u64 b) {
    asm("fma.rn.f32x2 %0, %1, %2, %0;" : "+l"(d) : "l"(a), "l"(b));
}
__device__ __forceinline__ u64 fmul2(u64 a, u64 b) {
    u64 d; asm("mul.rn.f32x2 %0, %1, %2;" : "=l"(d) : "l"(a), "l"(b)); return d;
}

// ======================= mma.sync helpers (sm_80+ path) =====================
__device__ __forceinline__ uint32_t smem_u32(const void* p) {
    uint32_t a;
    asm("{ .reg .u64 t; cvta.to.shared.u64 t, %1; cvt.u32.u64 %0, t; }"
        : "=r"(a) : "l"(p));
    return a;
}
__device__ __forceinline__ void cp_async16(uint32_t dst, const void* src) {
    asm volatile("cp.async.cg.shared.global [%0], [%1], 16;"
                 :: "r"(dst), "l"(src) : "memory");
}
__device__ __forceinline__ void cp_commit() {
    asm volatile("cp.async.commit_group;" ::: "memory");
}
template <int N_>
__device__ __forceinline__ void cp_wait() {
    asm volatile("cp.async.wait_group %0;" :: "n"(N_) : "memory");
}
__device__ __forceinline__ void ldsm4(uint32_t* r, uint32_t addr) {
    asm volatile("ldmatrix.sync.aligned.m8n8.x4.shared.b16 {%0,%1,%2,%3}, [%4];"
                 : "=r"(r[0]), "=r"(r[1]), "=r"(r[2]), "=r"(r[3]) : "r"(addr));
}
__device__ __forceinline__ void mma_bf16(float* c, const uint32_t* a, const uint32_t* b) {
    asm volatile(
        "mma.sync.aligned.m16n8k16.row.col.f32.bf16.bf16.f32 "
        "{%0,%1,%2,%3},{%4,%5,%6,%7},{%8,%9},{%0,%1,%2,%3};"
        : "+f"(c[0]), "+f"(c[1]), "+f"(c[2]), "+f"(c[3])
        : "r"(a[0]), "r"(a[1]), "r"(a[2]), "r"(a[3]), "r"(b[0]), "r"(b[1]));
}

// ======================= scratch (__device__ globals) =======================
__device__ float g_q[BATCH * NTOK * INNER];
__device__ float g_v[BATCH * NTOK * INNER];
__device__ float g_ao[BATCH * NTOK * INNER];
__device__ float g_norm[BATCH * HEADS * NTOK];

__device__ __nv_bfloat16 g_x_hi[BATCH * NTOK * DMODEL];
__device__ __nv_bfloat16 g_x_lo[BATCH * NTOK * DMODEL];
__device__ __nv_bfloat16 g_ao_hi[BATCH * NTOK * INNER];
__device__ __nv_bfloat16 g_ao_lo[BATCH * NTOK * INNER];
__device__ __nv_bfloat16 g_wq_hi[DMODEL * INNER];
__device__ __nv_bfloat16 g_wq_lo[DMODEL * INNER];
__device__ __nv_bfloat16 g_wv_hi[DMODEL * INNER];
__device__ __nv_bfloat16 g_wv_lo[DMODEL * INNER];
__device__ __nv_bfloat16 g_wo_hi[INNER * DMODEL];
__device__ __nv_bfloat16 g_wo_lo[INNER * DMODEL];

// ---------------------------------------------------------------------------
// split: fp32 -> bf16 hi + bf16 lo(residual).  4 elements / thread.
// ---------------------------------------------------------------------------
__global__ __launch_bounds__(256) void split_kernel(
    const float* __restrict__ A,
    __nv_bfloat16* __restrict__ hi, __nv_bfloat16* __restrict__ lo)
{
    int i = blockIdx.x * 256 + threadIdx.x;
    float4 v = ((const float4*)A)[i];
    __nv_bfloat16 hx = __float2bfloat16(v.x);
    __nv_bfloat16 hy = __float2bfloat16(v.y);
    __nv_bfloat16 hz = __float2bfloat16(v.z);
    __nv_bfloat16 hw = __float2bfloat16(v.w);
    __nv_bfloat162* hp = (__nv_bfloat162*)hi;
    __nv_bfloat162* lp = (__nv_bfloat162*)lo;
    hp[2 * i]     = __nv_bfloat162(hx, hy);
    hp[2 * i + 1] = __nv_bfloat162(hz, hw);
    lp[2 * i]     = __nv_bfloat162(__float2bfloat16(v.x - __bfloat162float(hx)),
                                   __float2bfloat16(v.y - __bfloat162float(hy)));
    lp[2 * i + 1] = __nv_bfloat162(__float2bfloat16(v.z - __bfloat162float(hz)),
                                   __float2bfloat16(v.w - __bfloat162float(hw)));
}

// ---------------------------------------------------------------------------
// split + transpose: W[K,N] fp32 -> T_hi/T_lo [N,K] bf16
// ---------------------------------------------------------------------------
__global__ __launch_bounds__(256) void split_transpose(
    const float* __restrict__ W,
    __nv_bfloat16* __restrict__ Thi, __nv_bfloat16* __restrict__ Tlo,
    int Kd, int Nd)
{
    __shared__ float t[32][33];
    int tx = threadIdx.x & 31, ty = threadIdx.x >> 5;
    int k0 = blockIdx.y * 32, n0 = blockIdx.x * 32;
    #pragma unroll
    for (int i = 0; i < 32; i += 8)
        t[ty + i][tx] = W[(size_t)(k0 + ty + i) * Nd + n0 + tx];
    __syncthreads();
    #pragma unroll
    for (int i = 0; i < 32; i += 8) {
        float v = t[tx][ty + i];
        __nv_bfloat16 h = __float2bfloat16(v);
        size_t o = (size_t)(n0 + ty + i) * Kd + k0 + tx;
        Thi[o] = h;
        Tlo[o] = __float2bfloat16(v - __bfloat162float(h));
    }
}

// ---------------------------------------------------------------------------
// HMMA GEMM (bf16x3 split): C[M,N] = (Ahi+Alo)[M,K] @ (Bhi+Blo)[N,K]^T + bias
// 128x128 CTA tile, 8 warps (64x32 each), K-chunk 32, double-buffered cp.async.
// smem rows padded to 40 bf16 (80B) -> conflict-free ldmatrix.
// ---------------------------------------------------------------------------
#define TPAD   40
#define TEN_B  (128 * TPAD * 2)       /* 10240 B per tensor tile */
#define STAGE_B (4 * TEN_B)           /* 40960 B per stage */

__device__ __forceinline__ void gemm_load_stage(
    uint32_t sbase, const char* const* g, const int* ro,
    size_t rowb, size_t koff, int tid)
{
    #pragma unroll
    for (int t = 0; t < 4; t++) {
        #pragma unroll
        for (int it = 0; it < 2; it++) {
            int idx = it * 256 + tid;
            int r = idx >> 2;
            int ch = (idx & 3) * 16;
            cp_async16(sbase + (uint32_t)(t * TEN_B + r * 80 + ch),
                       g[t] + (size_t)(ro[t] + r) * rowb + koff + ch);
        }
    }
    cp_commit();
}

__global__ __launch_bounds__(256) void gemm_mma(
    const __nv_bfloat16* __restrict__ Ahi_, const __nv_bfloat16* __restrict__ Alo_,
    const __nv_bfloat16* __restrict__ Bhi_, const __nv_bfloat16* __restrict__ Blo_,
    const float* __restrict__ bias, float* __restrict__ C, int N, int K)
{
    extern __shared__ char smem_raw[];
    const uint32_t sb = smem_u32(smem_raw);
    const int tid = threadIdx.x;
    const int lane = tid & 31, wid = tid >> 5;
    const int wm = wid >> 2, wn = wid & 3;       // warp grid 2(m) x 4(n)
    const int bm = blockIdx.y * 128, bn = blockIdx.x * 128;

    const char* g[4] = {(const char*)Ahi_, (const char*)Alo_,
                        (const char*)Bhi_, (const char*)Blo_};
    const int ro[4] = {bm, bm, bn, bn};
    const size_t rowb = (size_t)K * 2;

    // ldmatrix per-lane offsets (bytes). mid = 8x8 matrix id.
    const int mid = lane >> 3, lr = lane & 7;
    const uint32_t a_off = (uint32_t)(((mid & 1) * 8 + lr) * 80 + (mid >> 1) * 16);
    const uint32_t b_off = (uint32_t)(((mid >> 1) * 8 + lr) * 80 + (mid & 1) * 16);

    float acc[4][4][4];
    #pragma unroll
    for (int mf = 0; mf < 4; mf++)
        #pragma unroll
        for (int nf = 0; nf < 4; nf++)
            #pragma unroll
            for (int e = 0; e < 4; e++) acc[mf][nf][e] = 0.f;

    const int nch = K >> 5;                      // K-chunks of 32
    gemm_load_stage(sb, g, ro, rowb, 0, tid);

    for (int kc = 0; kc < nch; kc++) {
        if (kc + 1 < nch) {
            gemm_load_stage(sb + ((kc + 1) & 1) * STAGE_B, g, ro, rowb,
                            (size_t)(kc + 1) * 64, tid);
            cp_wait<1>();
        } else {
            cp_wait<0>();
        }
        __syncthreads();

        const uint32_t st = sb + (kc & 1) * STAGE_B;
        const uint32_t sAh = st, sAl = st + TEN_B;
        const uint32_t sBh = st + 2 * TEN_B, sBl = st + 3 * TEN_B;

        #pragma unroll
        for (int ks = 0; ks < 2; ks++) {
            const uint32_t kb = ks * 32;         // 16 bf16 = 32 B
            uint32_t ah[4][4], al[4][4], bh[2][4], bl[2][4];
            #pragma unroll
            for (int mf = 0; mf < 4; mf++) {
                uint32_t o = (uint32_t)((wm * 64 + mf * 16) * 80) + kb + a_off;
                ldsm4(ah[mf], sAh + o);
                ldsm4(al[mf], sAl + o);
            }
            #pragma unroll
            for (int nf2 = 0; nf2 < 2; nf2++) {
                uint32_t o = (uint32_t)((wn * 32 + nf2 * 16) * 80) + kb + b_off;
                ldsm4(bh[nf2], sBh + o);
                ldsm4(bl[nf2], sBl + o);
            }
            #pragma unroll
            for (int mf = 0; mf < 4; mf++)
                #pragma unroll
                for (int nf = 0; nf < 4; nf++) {
                    const uint32_t* B2h = &bh[nf >> 1][(nf & 1) * 2];
                    const uint32_t* B2l = &bl[nf >> 1][(nf & 1) * 2];
                    mma_bf16(acc[mf][nf], ah[mf], B2h);   // hi*hi
                    mma_bf16(acc[mf][nf], ah[mf], B2l);   // hi*lo
                    mma_bf16(acc[mf][nf], al[mf], B2h);   // lo*hi
                }
        }
        __syncthreads();
    }

    // epilogue: frag (mf,nf): rows wm*64+mf*16+{er, er+8}, cols wn*32+nf*8+ec..+1
    const int er = lane >> 2, ec = (lane & 3) * 2;
    #pragma unroll
    for (int nf = 0; nf < 4; nf++) {
        int gcol = bn + wn * 32 + nf * 8 + ec;
        float2 bv = *(const float2*)(bias + gcol);
        #pragma unroll
        for (int mf = 0; mf < 4; mf++) {
            int grow = bm + wm * 64 + mf * 16 + er;
            float2 o0 = make_float2(acc[mf][nf][0] + bv.x, acc[mf][nf][1] + bv.y);
            float2 o1 = make_float2(acc[mf][nf][2] + bv.x, acc[mf][nf][3] + bv.y);
            *(float2*)(C + (size_t)grow * N + gcol) = o0;
            *(float2*)(C + (size_t)(grow + 8) * N + gcol) = o1;
        }
    }
}

// ---------------------------------------------------------------------------
// Row norms
// ---------------------------------------------------------------------------
__global__ __launch_bounds__(256) void compute_norms(
    const float* __restrict__ q, float* __restrict__ norms)
{
    int idx = blockIdx.x * 256 + threadIdx.x;
    int n  = idx & (NTOK - 1);
    int bh = idx >> 11;
    int h = bh & (HEADS - 1);
    int b = bh >> 4;
    const float* p = q + ((size_t)(b * NTOK + n)) * INNER + h * DH;
    float s = 0.f;
    #pragma unroll
    for (int d = 0; d < DH; d += 4) {
        float4 t = *(const float4*)(p + d);
        s += t.x * t.x + t.y * t.y + t.z * t.z + t.w * t.w;
    }
    norms[idx] = s;
}

// ---------------------------------------------------------------------------
// Flash attention (k=q), f32x2 — unchanged from R6 best
// ---------------------------------------------------------------------------
#define QSTR 132
#define KSTR 68
#define VSTR 68
#define PSTR 132

__global__ __launch_bounds__(256) void attn_kernel(
    const float* __restrict__ q, const float* __restrict__ v,
    const float* __restrict__ norms, float* __restrict__ ao)
{
    extern __shared__ float sm[];
    float* Qs = sm;
    float* Ks = Qs + 64 * QSTR;
    float* Vs = Ks + 64 * KSTR;
    float* Ps = Vs + 64 * VSTR;
    float* kn = Ps + 64 * PSTR;

    const int tid = threadIdx.x;
    const int tx = tid & 15;
    const int ty = tid >> 4;
    const int i0 = blockIdx.x * 128;
    const int bh = blockIdx.y;
    const int h = bh & (HEADS - 1);
    const int b = bh >> 4;

    const float* qb = q + (size_t)b * NTOK * INNER + h * DH;
    const float* vb = v + (size_t)b * NTOK * INNER + h * DH;
    const float* nb = norms + (size_t)bh * NTOK;

    #pragma unroll
    for (int it = 0; it < 8; it++) {
        int idx = tid + it * 256;
        int r = idx >> 4;
        int d = (idx & 15) * 4;
        float4 t = *(const float4*)(qb + (size_t)(i0 + r) * INNER + d);
        Qs[(d + 0) * QSTR + r] = t.x;
        Qs[(d + 1) * QSTR + r] = t.y;
        Qs[(d + 2) * QSTR + r] = t.z;
        Qs[(d + 3) * QSTR + r] = t.w;
    }

    float m[8], l[8], corr[8];
    u64 acco[4][4];
    #pragma unroll
    for (int r = 0; r < 8; r++) { m[r] = -1e30f; l[r] = 0.f; }
    #pragma unroll
    for (int ip = 0; ip < 4; ip++)
        #pragma unroll
        for (int c = 0; c < 4; c++) acco[ip][c] = 0ull;

    for (int j0 = 0; j0 < NTOK; j0 += 64) {
        __syncthreads();

        #pragma unroll
        for (int it = 0; it < 4; it++) {
            int idx = tid + it * 256;
            int r = idx >> 4;
            int d = (idx & 15) * 4;
            float4 kt = *(const float4*)(qb + (size_t)(j0 + r) * INNER + d);
            Ks[(d + 0) * KSTR + r] = kt.x;
            Ks[(d + 1) * KSTR + r] = kt.y;
            Ks[(d + 2) * KSTR + r] = kt.z;
            Ks[(d + 3) * KSTR + r] = kt.w;
            float4 vt = *(const float4*)(vb + (size_t)(j0 + r) * INNER + d);
            *(float4*)&Vs[r * VSTR + d] = vt;
        }
        if (tid < 64) kn[tid] = nb[j0 + tid];
        __syncthreads();

        u64 accs[4][4];
        #pragma unroll
        for (int ip = 0; ip < 4; ip++)
            #pragma unroll
            for (int c = 0; c < 4; c++) accs[ip][c] = 0ull;

        #pragma unroll 4
        for (int kk = 0; kk < 64; kk++) {
            alignas(16) u64 a2[4];
            *(float4*)&a2[0] = *(const float4*)&Qs[kk * QSTR + ty * 8];
            *(float4*)&a2[2] = *(const float4*)&Qs[kk * QSTR + ty * 8 + 4];
            float4 kv = *(const float4*)&Ks[kk * KSTR + tx * 4];
            u64 b2[4];
            b2[0] = pack2(kv.x); b2[1] = pack2(kv.y);
            b2[2] = pack2(kv.z); b2[3] = pack2(kv.w);
            #pragma unroll
            for (int ip = 0; ip < 4; ip++)
                #pragma unroll
                for (int c = 0; c < 4; c++)
                    ffma2(accs[ip][c], a2[ip], b2[c]);
        }

        float lk[4];
        #pragma unroll
        for (int c = 0; c < 4; c++) lk[c] = kn[tx * 4 + c];

        float s[8][4];
        #pragma unroll
        for (int ip = 0; ip < 4; ip++)
            #pragma unroll
            for (int c = 0; c < 4; c++) {
                float2 t = unpack2(accs[ip][c]);
                s[2 * ip][c]     = (2.f * t.x - lk[c]) * SCALE;
                s[2 * ip + 1][c] = (2.f * t.y - lk[c]) * SCALE;
            }

        #pragma unroll
        for (int r = 0; r < 8; r++) {
            float mx = fmaxf(fmaxf(s[r][0], s[r][1]), fmaxf(s[r][2], s[r][3]));
            #pragma unroll
            for (int off = 8; off > 0; off >>= 1)
                mx = fmaxf(mx, __shfl_xor_sync(0xffffffffu, mx, off));
            float nm = fmaxf(m[r], mx);
            corr[r] = __expf(m[r] - nm);
            m[r] = nm;
            float rs = 0.f;
            #pragma unroll
            for (int c = 0; c < 4; c++) {
                s[r][c] = __expf(s[r][c] - nm);
                rs += s[r][c];
            }
            #pragma unroll
            for (int off = 8; off > 0; off >>= 1)
                rs += __shfl_xor_sync(0xffffffffu, rs, off);
            l[r] = l[r] * corr[r] + rs;
        }

        #pragma unroll
        for (int ip = 0; ip < 4; ip++) {
            u64 cp = pack2f(corr[2 * ip], corr[2 * ip + 1]);
            #pragma unroll
            for (int c = 0; c < 4; c++) acco[ip][c] = fmul2(acco[ip][c], cp);
        }

        #pragma unroll
        for (int c = 0; c < 4; c++) {
            int j = tx * 4 + c;
            float4 p0 = make_float4(s[0][c], s[1][c], s[2][c], s[3][c]);
            float4 p1 = make_float4(s[4][c], s[5][c], s[6][c], s[7][c]);
            *(float4*)&Ps[j * PSTR + ty * 8] = p0;
            *(float4*)&Ps[j * PSTR + ty * 8 + 4] = p1;
        }
        __syncthreads();

        #pragma unroll 2
        for (int j = 0; j < 64; j++) {
            alignas(16) u64 p2[4];
            *(float4*)&p2[0] = *(const float4*)&Ps[j * PSTR + ty * 8];
            *(float4*)&p2[2] = *(const float4*)&Ps[j * PSTR + ty * 8 + 4];
            float4 vv = *(const float4*)&Vs[j * VSTR + tx * 4];
            u64 v2[4];
            v2[0] = pack2(vv.x); v2[1] = pack2(vv.y);
            v2[2] = pack2(vv.z); v2[3] = pack2(vv.w);
            #pragma unroll
            for (int ip = 0; ip < 4; ip++)
                #pragma unroll
                for (int c = 0; c < 4; c++)
                    ffma2(acco[ip][c], p2[ip], v2[c]);
        }
    }

    float* ob = ao + ((size_t)b * NTOK + i0) * INNER + h * DH;
    #pragma unroll
    for (int ip = 0; ip < 4; ip++) {
        float2 o0 = unpack2(acco[ip][0]);
        float2 o1 = unpack2(acco[ip][1]);
        float2 o2 = unpack2(acco[ip][2]);
        float2 o3 = unpack2(acco[ip][3]);
        int r0 = ty * 8 + 2 * ip;
        float inv0 = 1.f / l[2 * ip];
        float inv1 = 1.f / l[2 * ip + 1];
        float4 w0 = make_float4(o0.x * inv0, o1.x * inv0, o2.x * inv0, o3.x * inv0);
        float4 w1 = make_float4(o0.y * inv1, o1.y * inv1, o2.y * inv1, o3.y * inv1);
        *(float4*)(ob + (size_t)r0 * INNER + tx * 4) = w0;
        *(float4*)(ob + (size_t)(r0 + 1) * INNER + tx * 4) = w1;
    }
}

// ---------------------------------------------------------------------------
extern "C" void kernel_launch(void* const* d_in, const int* in_sizes, int n_in,
                              void* d_out, int out_size)
{
    const float* x  = (const float*)d_in[0];
    const float* Wq = (const float*)d_in[1];
    const float* bq = (const float*)d_in[2];
    const float* Wv = (const float*)d_in[3];
    const float* bv = (const float*)d_in[4];
    const float* Wo = (const float*)d_in[5];
    const float* bo = (const float*)d_in[6];
    float* out = (float*)d_out;

    float *qp, *vp, *aop, *np;
    cudaGetSymbolAddress((void**)&qp,  g_q);
    cudaGetSymbolAddress((void**)&vp,  g_v);
    cudaGetSymbolAddress((void**)&aop, g_ao);
    cudaGetSymbolAddress((void**)&np,  g_norm);

    __nv_bfloat16 *xh, *xl, *aoh, *aol, *wqh, *wql, *wvh, *wvl, *woh, *wol;
    cudaGetSymbolAddress((void**)&xh,  g_x_hi);
    cudaGetSymbolAddress((void**)&xl,  g_x_lo);
    cudaGetSymbolAddress((void**)&aoh, g_ao_hi);
    cudaGetSymbolAddress((void**)&aol, g_ao_lo);
    cudaGetSymbolAddress((void**)&wqh, g_wq_hi);
    cudaGetSymbolAddress((void**)&wql, g_wq_lo);
    cudaGetSymbolAddress((void**)&wvh, g_wv_hi);
    cudaGetSymbolAddress((void**)&wvl, g_wv_lo);
    cudaGetSymbolAddress((void**)&woh, g_wo_hi);
    cudaGetSymbolAddress((void**)&wol, g_wo_lo);

    const int M = BATCH * NTOK;   // 8192

    // 1) splits
    split_kernel<<<(M * DMODEL) / 1024, 256>>>(x, xh, xl);
    split_transpose<<<dim3(INNER / 32, DMODEL / 32), 256>>>(Wq, wqh, wql, DMODEL, INNER);
    split_transpose<<<dim3(INNER / 32, DMODEL / 32), 256>>>(Wv, wvh, wvl, DMODEL, INNER);
    split_transpose<<<dim3(DMODEL / 32, INNER / 32), 256>>>(Wo, woh, wol, INNER, DMODEL);

    // 2) q/v projections on HMMA
    int gsmem = 2 * STAGE_B;   // 81920
    cudaFuncSetAttribute(gemm_mma,
                         cudaFuncAttributeMaxDynamicSharedMemorySize, gsmem);
    gemm_mma<<<dim3(INNER / 128, M / 128), 256, gsmem>>>(
        xh, xl, wqh, wql, bq, qp, INNER, DMODEL);
    gemm_mma<<<dim3(INNER / 128, M / 128), 256, gsmem>>>(
        xh, xl, wvh, wvl, bv, vp, INNER, DMODEL);

    // 3) attention (scalar f32x2 flash)
    compute_norms<<<(BATCH * HEADS * NTOK) / 256, 256>>>(qp, np);
    int asmem = (64 * QSTR + 64 * KSTR + 64 * VSTR + 64 * PSTR + 64) * (int)sizeof(float);
    cudaFuncSetAttribute(attn_kernel,
                         cudaFuncAttributeMaxDynamicSharedMemorySize, asmem);
    attn_kernel<<<dim3(NTOK / 128, BATCH * HEADS), 256, asmem>>>(qp, vp, np, aop);

    // 4) output projection on HMMA
    split_kernel<<<(M * INNER) / 1024, 256>>>(aop, aoh, aol);
    gemm_mma<<<dim3(DMODEL / 128, M / 128), 256, gsmem>>>(
        aoh, aol, woh, wol, bo, out, DMODEL, INNER);
}

// round 9
// speedup vs baseline: 1.3116x; 1.3116x over previous
#include <cuda_runtime.h>
#include <math.h>

#define BATCH 4
#define NTOK  2048
#define DMODEL 1024
#define HEADS 16
#define DH    64
#define INNER 1024
#define SCALE 0.125f                 /* 64^-0.5 */
#define CLOG2E 0.1803368801111f      /* SCALE * log2(e) */
#define TWO_C  0.3606737602222f      /* 2 * SCALE * log2(e) */

typedef unsigned long long u64;

__device__ __forceinline__ u64 pack2(float x) {
    u64 r; asm("mov.b64 %0, {%1, %1};" : "=l"(r) : "f"(x)); return r;
}
__device__ __forceinline__ float2 unpack2(u64 a) {
    float2 f; asm("mov.b64 {%0, %1}, %2;" : "=f"(f.x), "=f"(f.y) : "l"(a)); return f;
}
__device__ __forceinline__ void ffma2(u64 &d, u64 a, u64 b) {
    asm("fma.rn.f32x2 %0, %1, %2, %0;" : "+l"(d) : "l"(a), "l"(b));
}

// Scratch (allocation-free rule: __device__ globals)
__device__ float g_q[BATCH * NTOK * INNER];
__device__ float g_v[BATCH * NTOK * INNER];
__device__ float g_ao[BATCH * NTOK * INNER];
__device__ float g_norm[BATCH * HEADS * NTOK];   // ‖q‖² * SCALE * log2e

// ---------------------------------------------------------------------------
// SGEMM (f32x2): C[M,N] = A[M,K] @ W[K,N] + bias[N]   (R6-proven)
// ---------------------------------------------------------------------------
__global__ __launch_bounds__(256, 2) void sgemm_bias(
    const float* __restrict__ A, const float* __restrict__ W,
    const float* __restrict__ bias, float* __restrict__ C,
    int M, int N, int K)
{
    __shared__ float As[8][128];
    __shared__ float Bs[8][128];

    const int tid = threadIdx.x;
    const int bm = blockIdx.y * 128;
    const int bn = blockIdx.x * 128;
    const int tx = tid & 15;
    const int ty = tid >> 4;

    const int arow = tid >> 1;
    const int acol = (tid & 1) * 4;
    const int brow = tid >> 5;
    const int bcol = (tid & 31) * 4;

    const float* Ap = A + (size_t)(bm + arow) * K + acol;
    const float* Wp = W + (size_t)brow * N + bn + bcol;

    u64 acc[8][4];
    #pragma unroll
    for (int i = 0; i < 8; i++)
        #pragma unroll
        for (int j = 0; j < 4; j++) acc[i][j] = 0ull;

    for (int k0 = 0; k0 < K; k0 += 8) {
        float4 a4 = *(const float4*)(Ap + k0);
        As[acol + 0][arow] = a4.x;
        As[acol + 1][arow] = a4.y;
        As[acol + 2][arow] = a4.z;
        As[acol + 3][arow] = a4.w;
        *(float4*)&Bs[brow][bcol] = *(const float4*)(Wp + (size_t)k0 * N);
        __syncthreads();

        #pragma unroll
        for (int kk = 0; kk < 8; kk++) {
            float4 a0 = *(const float4*)&As[kk][ty * 8];
            float4 a1 = *(const float4*)&As[kk][ty * 8 + 4];
            alignas(16) u64 b2[4];
            *(float4*)&b2[0] = *(const float4*)&Bs[kk][tx * 4];
            *(float4*)&b2[2] = *(const float4*)&Bs[kk][64 + tx * 4];
            u64 ad[8];
            ad[0] = pack2(a0.x); ad[1] = pack2(a0.y);
            ad[2] = pack2(a0.z); ad[3] = pack2(a0.w);
            ad[4] = pack2(a1.x); ad[5] = pack2(a1.y);
            ad[6] = pack2(a1.z); ad[7] = pack2(a1.w);
            #pragma unroll
            for (int i = 0; i < 8; i++)
                #pragma unroll
                for (int j = 0; j < 4; j++)
                    ffma2(acc[i][j], ad[i], b2[j]);
        }
        __syncthreads();
    }

    float4 bb0 = *(const float4*)(bias + bn + tx * 4);
    float4 bb1 = *(const float4*)(bias + bn + 64 + tx * 4);

    #pragma unroll
    for (int i = 0; i < 8; i++) {
        float* Cp = C + (size_t)(bm + ty * 8 + i) * N + bn;
        float2 p0 = unpack2(acc[i][0]), p1 = unpack2(acc[i][1]);
        float2 p2 = unpack2(acc[i][2]), p3 = unpack2(acc[i][3]);
        float4 o0 = make_float4(p0.x + bb0.x, p0.y + bb0.y, p1.x + bb0.z, p1.y + bb0.w);
        float4 o1 = make_float4(p2.x + bb1.x, p2.y + bb1.y, p3.x + bb1.z, p3.y + bb1.w);
        *(float4*)(Cp + tx * 4) = o0;
        *(float4*)(Cp + 64 + tx * 4) = o1;
    }
}

// ---------------------------------------------------------------------------
// Row norms, pre-scaled by SCALE*log2(e)
// ---------------------------------------------------------------------------
__global__ __launch_bounds__(256) void compute_norms(
    const float* __restrict__ q, float* __restrict__ norms)
{
    int idx = blockIdx.x * 256 + threadIdx.x;
    int n  = idx & (NTOK - 1);
    int bh = idx >> 11;
    int h = bh & (HEADS - 1);
    int b = bh >> 4;
    const float* p = q + ((size_t)(b * NTOK + n)) * INNER + h * DH;
    float s = 0.f;
    #pragma unroll
    for (int d = 0; d < DH; d += 4) {
        float4 t = *(const float4*)(p + d);
        s += t.x * t.x + t.y * t.y + t.z * t.z + t.w * t.w;
    }
    norms[idx] = s * CLOG2E;
}

// ---------------------------------------------------------------------------
// Flash attention (k=q), f32x2, NO online softmax:
//   s_ij = (2 q_i.q_j - |q_i|^2 - |q_j|^2) * SCALE  <= 0,  max == 0 (j=i)
//   p = exp2f(ab*2C - aaC - bbC),  l = plain running sum (no rescale).
// i-tile 128, j-tile 64, 256 threads, per-thread 8i x 4j (i in f32x2 pairs).
// ---------------------------------------------------------------------------
#define QSTR 132
#define KSTR 68
#define VSTR 68
#define PSTR 132

__global__ __launch_bounds__(256) void attn_kernel(
    const float* __restrict__ q, const float* __restrict__ v,
    const float* __restrict__ norms, float* __restrict__ ao)
{
    extern __shared__ float sm[];
    float* Qs = sm;
    float* Ks = Qs + 64 * QSTR;
    float* Vs = Ks + 64 * KSTR;
    float* Ps = Vs + 64 * VSTR;
    float* kn = Ps + 64 * PSTR;

    const int tid = threadIdx.x;
    const int tx = tid & 15;
    const int ty = tid >> 4;
    const int i0 = blockIdx.x * 128;
    const int bh = blockIdx.y;
    const int h = bh & (HEADS - 1);
    const int b = bh >> 4;

    const float* qb = q + (size_t)b * NTOK * INNER + h * DH;
    const float* vb = v + (size_t)b * NTOK * INNER + h * DH;
    const float* nb = norms + (size_t)bh * NTOK;

    // Q tile transposed: Qs[d][i]
    #pragma unroll
    for (int it = 0; it < 8; it++) {
        int idx = tid + it * 256;
        int r = idx >> 4;
        int d = (idx & 15) * 4;
        float4 t = *(const float4*)(qb + (size_t)(i0 + r) * INNER + d);
        Qs[(d + 0) * QSTR + r] = t.x;
        Qs[(d + 1) * QSTR + r] = t.y;
        Qs[(d + 2) * QSTR + r] = t.z;
        Qs[(d + 3) * QSTR + r] = t.w;
    }

    // per-thread row norms (pre-scaled) and plain l accumulators
    float aaC[8], lsum[8];
    #pragma unroll
    for (int r = 0; r < 8; r++) {
        aaC[r] = __ldg(nb + i0 + ty * 8 + r);
        lsum[r] = 0.f;
    }

    u64 acco[4][4];
    #pragma unroll
    for (int ip = 0; ip < 4; ip++)
        #pragma unroll
        for (int c = 0; c < 4; c++) acco[ip][c] = 0ull;

    for (int j0 = 0; j0 < NTOK; j0 += 64) {
        __syncthreads();   // prev-tile smem reads done (also fences Q store)

        // K transposed + V natural + norms
        #pragma unroll
        for (int it = 0; it < 4; it++) {
            int idx = tid + it * 256;
            int r = idx >> 4;
            int d = (idx & 15) * 4;
            float4 kt = *(const float4*)(qb + (size_t)(j0 + r) * INNER + d);
            Ks[(d + 0) * KSTR + r] = kt.x;
            Ks[(d + 1) * KSTR + r] = kt.y;
            Ks[(d + 2) * KSTR + r] = kt.z;
            Ks[(d + 3) * KSTR + r] = kt.w;
            float4 vt = *(const float4*)(vb + (size_t)(j0 + r) * INNER + d);
            *(float4*)&Vs[r * VSTR + d] = vt;
        }
        if (tid < 64) kn[tid] = nb[j0 + tid];
        __syncthreads();

        // ---- S = Q @ K^T, f32x2 pairs over i ----
        u64 accs[4][4];
        #pragma unroll
        for (int ip = 0; ip < 4; ip++)
            #pragma unroll
            for (int c = 0; c < 4; c++) accs[ip][c] = 0ull;

        #pragma unroll 4
        for (int kk = 0; kk < 64; kk++) {
            alignas(16) u64 a2[4];
            *(float4*)&a2[0] = *(const float4*)&Qs[kk * QSTR + ty * 8];
            *(float4*)&a2[2] = *(const float4*)&Qs[kk * QSTR + ty * 8 + 4];
            float4 kv = *(const float4*)&Ks[kk * KSTR + tx * 4];
            u64 b2[4];
            b2[0] = pack2(kv.x); b2[1] = pack2(kv.y);
            b2[2] = pack2(kv.z); b2[3] = pack2(kv.w);
            #pragma unroll
            for (int ip = 0; ip < 4; ip++)
                #pragma unroll
                for (int c = 0; c < 4; c++)
                    ffma2(accs[ip][c], a2[ip], b2[c]);
        }

        // ---- p = exp2(ab*2C - aaC - bbC); plain l accumulation ----
        float bbC[4];
        #pragma unroll
        for (int c = 0; c < 4; c++) bbC[c] = kn[tx * 4 + c];

        float p[8][4];
        #pragma unroll
        for (int ip = 0; ip < 4; ip++) {
            const float a0 = aaC[2 * ip], a1 = aaC[2 * ip + 1];
            #pragma unroll
            for (int c = 0; c < 4; c++) {
                float2 t = unpack2(accs[ip][c]);
                float p0 = exp2f(fmaf(t.x, TWO_C, -a0) - bbC[c]);
                float p1 = exp2f(fmaf(t.y, TWO_C, -a1) - bbC[c]);
                p[2 * ip][c] = p0;
                p[2 * ip + 1][c] = p1;
                lsum[2 * ip] += p0;
                lsum[2 * ip + 1] += p1;
            }
        }

        __syncthreads();   // everyone done reading Ks as K

        // store P (j-major, i contiguous)
        #pragma unroll
        for (int c = 0; c < 4; c++) {
            int j = tx * 4 + c;
            float4 p0 = make_float4(p[0][c], p[1][c], p[2][c], p[3][c]);
            float4 p1 = make_float4(p[4][c], p[5][c], p[6][c], p[7][c]);
            *(float4*)&Ps[j * PSTR + ty * 8] = p0;
            *(float4*)&Ps[j * PSTR + ty * 8 + 4] = p1;
        }
        __syncthreads();

        // ---- acco += P @ V (no rescale ever) ----
        #pragma unroll 2
        for (int j = 0; j < 64; j++) {
            alignas(16) u64 p2[4];
            *(float4*)&p2[0] = *(const float4*)&Ps[j * PSTR + ty * 8];
            *(float4*)&p2[2] = *(const float4*)&Ps[j * PSTR + ty * 8 + 4];
            float4 vv = *(const float4*)&Vs[j * VSTR + tx * 4];
            u64 v2[4];
            v2[0] = pack2(vv.x); v2[1] = pack2(vv.y);
            v2[2] = pack2(vv.z); v2[3] = pack2(vv.w);
            #pragma unroll
            for (int ip = 0; ip < 4; ip++)
                #pragma unroll
                for (int c = 0; c < 4; c++)
                    ffma2(acco[ip][c], p2[ip], v2[c]);
        }
    }

    // single final l reduction over the 16 tx lanes (xor stays in-group)
    float inv[8];
    #pragma unroll
    for (int r = 0; r < 8; r++) {
        float lv = lsum[r];
        #pragma unroll
        for (int off = 8; off > 0; off >>= 1)
            lv += __shfl_xor_sync(0xffffffffu, lv, off);
        inv[r] = 1.f / lv;
    }

    // epilogue
    float* ob = ao + ((size_t)b * NTOK + i0) * INNER + h * DH;
    #pragma unroll
    for (int ip = 0; ip < 4; ip++) {
        float2 o0 = unpack2(acco[ip][0]);
        float2 o1 = unpack2(acco[ip][1]);
        float2 o2 = unpack2(acco[ip][2]);
        float2 o3 = unpack2(acco[ip][3]);
        int r0 = ty * 8 + 2 * ip;
        float inv0 = inv[2 * ip];
        float inv1 = inv[2 * ip + 1];
        float4 w0 = make_float4(o0.x * inv0, o1.x * inv0, o2.x * inv0, o3.x * inv0);
        float4 w1 = make_float4(o0.y * inv1, o1.y * inv1, o2.y * inv1, o3.y * inv1);
        *(float4*)(ob + (size_t)r0 * INNER + tx * 4) = w0;
        *(float4*)(ob + (size_t)(r0 + 1) * INNER + tx * 4) = w1;
    }
}

// ---------------------------------------------------------------------------
extern "C" void kernel_launch(void* const* d_in, const int* in_sizes, int n_in,
                              void* d_out, int out_size)
{
    const float* x  = (const float*)d_in[0];
    const float* Wq = (const float*)d_in[1];
    const float* bq = (const float*)d_in[2];
    const float* Wv = (const float*)d_in[3];
    const float* bv = (const float*)d_in[4];
    const float* Wo = (const float*)d_in[5];
    const float* bo = (const float*)d_in[6];
    float* out = (float*)d_out;

    float *qp, *vp, *aop, *np;
    cudaGetSymbolAddress((void**)&qp,  g_q);
    cudaGetSymbolAddress((void**)&vp,  g_v);
    cudaGetSymbolAddress((void**)&aop, g_ao);
    cudaGetSymbolAddress((void**)&np,  g_norm);

    const int M = BATCH * NTOK;   // 8192

    dim3 ggp(INNER / 128, M / 128);
    sgemm_bias<<<ggp, 256>>>(x, Wq, bq, qp, M, INNER, DMODEL);
    sgemm_bias<<<ggp, 256>>>(x, Wv, bv, vp, M, INNER, DMODEL);

    compute_norms<<<(BATCH * HEADS * NTOK) / 256, 256>>>(qp, np);

    int smem = (64 * QSTR + 64 * KSTR + 64 * VSTR + 64 * PSTR + 64) * (int)sizeof(float);
    cudaFuncSetAttribute(attn_kernel,
                         cudaFuncAttributeMaxDynamicSharedMemorySize, smem);
    attn_kernel<<<dim3(NTOK / 128, BATCH * HEADS), 256, smem>>>(qp, vp, np, aop);

    sgemm_bias<<<dim3(DMODEL / 128, M / 128), 256>>>(aop, Wo, bo, out, M, DMODEL, INNER);
}

// round 10
// speedup vs baseline: 1.4280x; 1.0887x over previous
#include <cuda_runtime.h>
#include <math.h>

#define BATCH 4
#define NTOK  2048
#define DMODEL 1024
#define HEADS 16
#define DH    64
#define INNER 1024
#define SCALE 0.125f                 /* 64^-0.5 */
#define CLOG2E 0.1803368801111f      /* SCALE * log2(e) */
#define TWO_C  0.3606737602222f      /* 2 * SCALE * log2(e) */

typedef unsigned long long u64;

__device__ __forceinline__ u64 pack2(float x) {
    u64 r; asm("mov.b64 %0, {%1, %1};" : "=l"(r) : "f"(x)); return r;
}
__device__ __forceinline__ float2 unpack2(u64 a) {
    float2 f; asm("mov.b64 {%0, %1}, %2;" : "=f"(f.x), "=f"(f.y) : "l"(a)); return f;
}
__device__ __forceinline__ void ffma2(u64 &d, u64 a, u64 b) {
    asm("fma.rn.f32x2 %0, %1, %2, %0;" : "+l"(d) : "l"(a), "l"(b));
}

// Scratch (allocation-free rule: __device__ globals)
__device__ float g_q[BATCH * NTOK * INNER];
__device__ float g_v[BATCH * NTOK * INNER];
__device__ float g_ao[BATCH * NTOK * INNER];
__device__ float g_norm[BATCH * HEADS * NTOK];   // ‖q‖² * SCALE * log2e

// ---------------------------------------------------------------------------
// SGEMM (f32x2, double-buffered, dual-output):
//   set = blockIdx.x >> 3 selects {W0,b0,C0} or {W1,b1,C1} (same A).
//   C[M,1024] = A[M,K] @ W[K,1024] + b.  One __syncthreads per K-stage.
// ---------------------------------------------------------------------------
__global__ __launch_bounds__(256, 2) void sgemm_dual(
    const float* __restrict__ A,
    const float* __restrict__ W0, const float* __restrict__ b0, float* __restrict__ C0,
    const float* __restrict__ W1, const float* __restrict__ b1, float* __restrict__ C1,
    int M, int N, int K)
{
    __shared__ float As[2][8][128];   // [stage][k][m] transposed
    __shared__ float Bs[2][8][128];   // [stage][k][n]

    const int tid = threadIdx.x;
    const int set = blockIdx.x >> 3;
    const int bn = (blockIdx.x & 7) * 128;
    const int bm = blockIdx.y * 128;
    const int tx = tid & 15;
    const int ty = tid >> 4;

    const float* W    = set ? W1 : W0;
    const float* bias = set ? b1 : b0;
    float*       C    = set ? C1 : C0;

    const int arow = tid >> 1;
    const int acol = (tid & 1) * 4;
    const int brow = tid >> 5;
    const int bcol = (tid & 31) * 4;

    const float* Ap = A + (size_t)(bm + arow) * K + acol;
    const float* Wp = W + (size_t)brow * N + bn + bcol;

    u64 acc[8][4];
    #pragma unroll
    for (int i = 0; i < 8; i++)
        #pragma unroll
        for (int j = 0; j < 4; j++) acc[i][j] = 0ull;

    // prologue: stage 0 into buffer 0
    {
        float4 a4 = *(const float4*)Ap;
        As[0][acol + 0][arow] = a4.x;
        As[0][acol + 1][arow] = a4.y;
        As[0][acol + 2][arow] = a4.z;
        As[0][acol + 3][arow] = a4.w;
        *(float4*)&Bs[0][brow][bcol] = *(const float4*)Wp;
    }
    __syncthreads();

    const int nst = K >> 3;
    for (int s = 0; s < nst; s++) {
        const int cur = s & 1;
        float4 na, nb;
        const bool more = (s + 1 < nst);
        if (more) {
            na = *(const float4*)(Ap + (s + 1) * 8);
            nb = *(const float4*)(Wp + (size_t)(s + 1) * 8 * N);
        }

        #pragma unroll
        for (int kk = 0; kk < 8; kk++) {
            float4 a0 = *(const float4*)&As[cur][kk][ty * 8];
            float4 a1 = *(const float4*)&As[cur][kk][ty * 8 + 4];
            alignas(16) u64 b2[4];
            *(float4*)&b2[0] = *(const float4*)&Bs[cur][kk][tx * 4];
            *(float4*)&b2[2] = *(const float4*)&Bs[cur][kk][64 + tx * 4];
            u64 ad[8];
            ad[0] = pack2(a0.x); ad[1] = pack2(a0.y);
            ad[2] = pack2(a0.z); ad[3] = pack2(a0.w);
            ad[4] = pack2(a1.x); ad[5] = pack2(a1.y);
            ad[6] = pack2(a1.z); ad[7] = pack2(a1.w);
            #pragma unroll
            for (int i = 0; i < 8; i++)
                #pragma unroll
                for (int j = 0; j < 4; j++)
                    ffma2(acc[i][j], ad[i], b2[j]);
        }

        if (more) {
            const int nxt = cur ^ 1;
            As[nxt][acol + 0][arow] = na.x;
            As[nxt][acol + 1][arow] = na.y;
            As[nxt][acol + 2][arow] = na.z;
            As[nxt][acol + 3][arow] = na.w;
            *(float4*)&Bs[nxt][brow][bcol] = nb;
            __syncthreads();
        }
    }

    float4 bb0 = *(const float4*)(bias + bn + tx * 4);
    float4 bb1 = *(const float4*)(bias + bn + 64 + tx * 4);

    #pragma unroll
    for (int i = 0; i < 8; i++) {
        float* Cp = C + (size_t)(bm + ty * 8 + i) * N + bn;
        float2 p0 = unpack2(acc[i][0]), p1 = unpack2(acc[i][1]);
        float2 p2 = unpack2(acc[i][2]), p3 = unpack2(acc[i][3]);
        float4 o0 = make_float4(p0.x + bb0.x, p0.y + bb0.y, p1.x + bb0.z, p1.y + bb0.w);
        float4 o1 = make_float4(p2.x + bb1.x, p2.y + bb1.y, p3.x + bb1.z, p3.y + bb1.w);
        *(float4*)(Cp + tx * 4) = o0;
        *(float4*)(Cp + 64 + tx * 4) = o1;
    }
}

// ---------------------------------------------------------------------------
// Row norms, pre-scaled by SCALE*log2(e)
// ---------------------------------------------------------------------------
__global__ __launch_bounds__(256) void compute_norms(
    const float* __restrict__ q, float* __restrict__ norms)
{
    int idx = blockIdx.x * 256 + threadIdx.x;
    int n  = idx & (NTOK - 1);
    int bh = idx >> 11;
    int h = bh & (HEADS - 1);
    int b = bh >> 4;
    const float* p = q + ((size_t)(b * NTOK + n)) * INNER + h * DH;
    float s = 0.f;
    #pragma unroll
    for (int d = 0; d < DH; d += 4) {
        float4 t = *(const float4*)(p + d);
        s += t.x * t.x + t.y * t.y + t.z * t.z + t.w * t.w;
    }
    norms[idx] = s * CLOG2E;
}

// ---------------------------------------------------------------------------
// Flash attention (k=q), f32x2, no online softmax (R9-proven):
//   p = exp2(qk*2C - aaC - bbC) <= 1,  l = plain sum, single final reduction.
// ---------------------------------------------------------------------------
#define QSTR 132
#define KSTR 68
#define VSTR 68
#define PSTR 132

__global__ __launch_bounds__(256) void attn_kernel(
    const float* __restrict__ q, const float* __restrict__ v,
    const float* __restrict__ norms, float* __restrict__ ao)
{
    extern __shared__ float sm[];
    float* Qs = sm;
    float* Ks = Qs + 64 * QSTR;
    float* Vs = Ks + 64 * KSTR;
    float* Ps = Vs + 64 * VSTR;
    float* kn = Ps + 64 * PSTR;

    const int tid = threadIdx.x;
    const int tx = tid & 15;
    const int ty = tid >> 4;
    const int i0 = blockIdx.x * 128;
    const int bh = blockIdx.y;
    const int h = bh & (HEADS - 1);
    const int b = bh >> 4;

    const float* qb = q + (size_t)b * NTOK * INNER + h * DH;
    const float* vb = v + (size_t)b * NTOK * INNER + h * DH;
    const float* nb = norms + (size_t)bh * NTOK;

    #pragma unroll
    for (int it = 0; it < 8; it++) {
        int idx = tid + it * 256;
        int r = idx >> 4;
        int d = (idx & 15) * 4;
        float4 t = *(const float4*)(qb + (size_t)(i0 + r) * INNER + d);
        Qs[(d + 0) * QSTR + r] = t.x;
        Qs[(d + 1) * QSTR + r] = t.y;
        Qs[(d + 2) * QSTR + r] = t.z;
        Qs[(d + 3) * QSTR + r] = t.w;
    }

    float aaC[8], lsum[8];
    #pragma unroll
    for (int r = 0; r < 8; r++) {
        aaC[r] = __ldg(nb + i0 + ty * 8 + r);
        lsum[r] = 0.f;
    }

    u64 acco[4][4];
    #pragma unroll
    for (int ip = 0; ip < 4; ip++)
        #pragma unroll
        for (int c = 0; c < 4; c++) acco[ip][c] = 0ull;

    for (int j0 = 0; j0 < NTOK; j0 += 64) {
        __syncthreads();

        #pragma unroll
        for (int it = 0; it < 4; it++) {
            int idx = tid + it * 256;
            int r = idx >> 4;
            int d = (idx & 15) * 4;
            float4 kt = *(const float4*)(qb + (size_t)(j0 + r) * INNER + d);
            Ks[(d + 0) * KSTR + r] = kt.x;
            Ks[(d + 1) * KSTR + r] = kt.y;
            Ks[(d + 2) * KSTR + r] = kt.z;
            Ks[(d + 3) * KSTR + r] = kt.w;
            float4 vt = *(const float4*)(vb + (size_t)(j0 + r) * INNER + d);
            *(float4*)&Vs[r * VSTR + d] = vt;
        }
        if (tid < 64) kn[tid] = nb[j0 + tid];
        __syncthreads();

        u64 accs[4][4];
        #pragma unroll
        for (int ip = 0; ip < 4; ip++)
            #pragma unroll
            for (int c = 0; c < 4; c++) accs[ip][c] = 0ull;

        #pragma unroll 4
        for (int kk = 0; kk < 64; kk++) {
            alignas(16) u64 a2[4];
            *(float4*)&a2[0] = *(const float4*)&Qs[kk * QSTR + ty * 8];
            *(float4*)&a2[2] = *(const float4*)&Qs[kk * QSTR + ty * 8 + 4];
            float4 kv = *(const float4*)&Ks[kk * KSTR + tx * 4];
            u64 b2[4];
            b2[0] = pack2(kv.x); b2[1] = pack2(kv.y);
            b2[2] = pack2(kv.z); b2[3] = pack2(kv.w);
            #pragma unroll
            for (int ip = 0; ip < 4; ip++)
                #pragma unroll
                for (int c = 0; c < 4; c++)
                    ffma2(accs[ip][c], a2[ip], b2[c]);
        }

        float bbC[4];
        #pragma unroll
        for (int c = 0; c < 4; c++) bbC[c] = kn[tx * 4 + c];

        float p[8][4];
        #pragma unroll
        for (int ip = 0; ip < 4; ip++) {
            const float a0 = aaC[2 * ip], a1 = aaC[2 * ip + 1];
            #pragma unroll
            for (int c = 0; c < 4; c++) {
                float2 t = unpack2(accs[ip][c]);
                float p0 = exp2f(fmaf(t.x, TWO_C, -a0) - bbC[c]);
                float p1 = exp2f(fmaf(t.y, TWO_C, -a1) - bbC[c]);
                p[2 * ip][c] = p0;
                p[2 * ip + 1][c] = p1;
                lsum[2 * ip] += p0;
                lsum[2 * ip + 1] += p1;
            }
        }

        __syncthreads();

        #pragma unroll
        for (int c = 0; c < 4; c++) {
            int j = tx * 4 + c;
            float4 p0 = make_float4(p[0][c], p[1][c], p[2][c], p[3][c]);
            float4 p1 = make_float4(p[4][c], p[5][c], p[6][c], p[7][c]);
            *(float4*)&Ps[j * PSTR + ty * 8] = p0;
            *(float4*)&Ps[j * PSTR + ty * 8 + 4] = p1;
        }
        __syncthreads();

        #pragma unroll 2
        for (int j = 0; j < 64; j++) {
            alignas(16) u64 p2[4];
            *(float4*)&p2[0] = *(const float4*)&Ps[j * PSTR + ty * 8];
            *(float4*)&p2[2] = *(const float4*)&Ps[j * PSTR + ty * 8 + 4];
            float4 vv = *(const float4*)&Vs[j * VSTR + tx * 4];
            u64 v2[4];
            v2[0] = pack2(vv.x); v2[1] = pack2(vv.y);
            v2[2] = pack2(vv.z); v2[3] = pack2(vv.w);
            #pragma unroll
            for (int ip = 0; ip < 4; ip++)
                #pragma unroll
                for (int c = 0; c < 4; c++)
                    ffma2(acco[ip][c], p2[ip], v2[c]);
        }
    }

    float inv[8];
    #pragma unroll
    for (int r = 0; r < 8; r++) {
        float lv = lsum[r];
        #pragma unroll
        for (int off = 8; off > 0; off >>= 1)
            lv += __shfl_xor_sync(0xffffffffu, lv, off);
        inv[r] = 1.f / lv;
    }

    float* ob = ao + ((size_t)b * NTOK + i0) * INNER + h * DH;
    #pragma unroll
    for (int ip = 0; ip < 4; ip++) {
        float2 o0 = unpack2(acco[ip][0]);
        float2 o1 = unpack2(acco[ip][1]);
        float2 o2 = unpack2(acco[ip][2]);
        float2 o3 = unpack2(acco[ip][3]);
        int r0 = ty * 8 + 2 * ip;
        float inv0 = inv[2 * ip];
        float inv1 = inv[2 * ip + 1];
        float4 w0 = make_float4(o0.x * inv0, o1.x * inv0, o2.x * inv0, o3.x * inv0);
        float4 w1 = make_float4(o0.y * inv1, o1.y * inv1, o2.y * inv1, o3.y * inv1);
        *(float4*)(ob + (size_t)r0 * INNER + tx * 4) = w0;
        *(float4*)(ob + (size_t)(r0 + 1) * INNER + tx * 4) = w1;
    }
}

// ---------------------------------------------------------------------------
extern "C" void kernel_launch(void* const* d_in, const int* in_sizes, int n_in,
                              void* d_out, int out_size)
{
    const float* x  = (const float*)d_in[0];
    const float* Wq = (const float*)d_in[1];
    const float* bq = (const float*)d_in[2];
    const float* Wv = (const float*)d_in[3];
    const float* bv = (const float*)d_in[4];
    const float* Wo = (const float*)d_in[5];
    const float* bo = (const float*)d_in[6];
    float* out = (float*)d_out;

    float *qp, *vp, *aop, *np;
    cudaGetSymbolAddress((void**)&qp,  g_q);
    cudaGetSymbolAddress((void**)&vp,  g_v);
    cudaGetSymbolAddress((void**)&aop, g_ao);
    cudaGetSymbolAddress((void**)&np,  g_norm);

    const int M = BATCH * NTOK;   // 8192

    // fused q+v projection: blocks 0..7 -> Wq/q, 8..15 -> Wv/v
    sgemm_dual<<<dim3(16, M / 128), 256>>>(
        x, Wq, bq, qp, Wv, bv, vp, M, INNER, DMODEL);

    compute_norms<<<(BATCH * HEADS * NTOK) / 256, 256>>>(qp, np);

    int smem = (64 * QSTR + 64 * KSTR + 64 * VSTR + 64 * PSTR + 64) * (int)sizeof(float);
    cudaFuncSetAttribute(attn_kernel,
                         cudaFuncAttributeMaxDynamicSharedMemorySize, smem);
    attn_kernel<<<dim3(NTOK / 128, BATCH * HEADS), 256, smem>>>(qp, vp, np, aop);

    // output projection (single set: both slots point at Wo)
    sgemm_dual<<<dim3(8, M / 128), 256>>>(
        aop, Wo, bo, out, Wo, bo, out, M, DMODEL, INNER);
}